// round 2
// baseline (speedup 1.0000x reference)
#include <cuda_runtime.h>
#include <cuda_bf16.h>

// Haar 2x2 DWT: x[16,64,256,256] f32 -> out[16,256,128,128] f32
//   out[n][k*C + c][h2][w2], k = 2*(row parity) + (col parity) of the Haar basis
//   a = x[..][2h2][2w2], b = x[..][2h2][2w2+1], cc = x[..][2h2+1][2w2], d = x[..][2h2+1][2w2+1]
//   k0 = .5(a+b+cc+d); k1 = .5(a+b-cc-d); k2 = .5(a-b+cc-d); k3 = .5(a-b-cc+d)
//
// Round 2: 16 input cols x 2 rows per thread (8x float4 streaming loads, MLP=8),
// 8x float4 streaming stores (2 per subband). Evict-first (.cs) hints both ways.

#define N_    16
#define C_    64
#define H_    256
#define W_    256
#define H2_   (H_/2)    // 128
#define W2_   (W_/2)    // 128
#define W4IN  (W_/4)    // 64 float4 per input row
#define W4OUT (W2_/4)   // 32 float4 per output row
#define TPATCH 16       // threads per row-pair: W_/16

__device__ __forceinline__ void haar4(float a, float b, float cc, float d,
                                      float& k0, float& k1, float& k2, float& k3) {
    float s0 = a + b, s1 = cc + d, d0 = a - b, d1 = cc - d;
    k0 = 0.5f * (s0 + s1);
    k1 = 0.5f * (s0 - s1);
    k2 = 0.5f * (d0 + d1);
    k3 = 0.5f * (d0 - d1);
}

__global__ __launch_bounds__(256)
void dwt2_haar_kernel(const float* __restrict__ x, float* __restrict__ out) {
    unsigned tid = blockIdx.x * blockDim.x + threadIdx.x;
    // tid = ((n*C_ + c)*H2_ + h2)*TPATCH + w16
    unsigned w16  = tid & (TPATCH - 1);
    unsigned rest = tid >> 4;
    unsigned h2   = rest & (H2_ - 1);
    rest >>= 7;
    unsigned c    = rest & (C_ - 1);
    unsigned n    = rest >> 6;

    const float4* xv = (const float4*)x;
    unsigned row0 = (n * C_ + c) * H_ + 2u * h2;
    unsigned ib   = row0 * W4IN + w16 * 4u;

    // 8 front-batched streaming loads (top row 4, bottom row 4)
    float4 t0 = __ldcs(&xv[ib + 0]);
    float4 t1 = __ldcs(&xv[ib + 1]);
    float4 t2 = __ldcs(&xv[ib + 2]);
    float4 t3 = __ldcs(&xv[ib + 3]);
    float4 b0 = __ldcs(&xv[ib + 0 + W4IN]);
    float4 b1 = __ldcs(&xv[ib + 1 + W4IN]);
    float4 b2 = __ldcs(&xv[ib + 2 + W4IN]);
    float4 b3 = __ldcs(&xv[ib + 3 + W4IN]);

    // Subband outputs: 2 float4 each (8 output cols)
    float4 o0a, o0b, o1a, o1b, o2a, o2b, o3a, o3b;

    haar4(t0.x, t0.y, b0.x, b0.y, o0a.x, o1a.x, o2a.x, o3a.x);
    haar4(t0.z, t0.w, b0.z, b0.w, o0a.y, o1a.y, o2a.y, o3a.y);
    haar4(t1.x, t1.y, b1.x, b1.y, o0a.z, o1a.z, o2a.z, o3a.z);
    haar4(t1.z, t1.w, b1.z, b1.w, o0a.w, o1a.w, o2a.w, o3a.w);
    haar4(t2.x, t2.y, b2.x, b2.y, o0b.x, o1b.x, o2b.x, o3b.x);
    haar4(t2.z, t2.w, b2.z, b2.w, o0b.y, o1b.y, o2b.y, o3b.y);
    haar4(t3.x, t3.y, b3.x, b3.y, o0b.z, o1b.z, o2b.z, o3b.z);
    haar4(t3.z, t3.w, b3.z, b3.w, o0b.w, o1b.w, o2b.w, o3b.w);

    float4* ov = (float4*)out;
    unsigned plane = n * (4u * C_) + c;                  // k=0 plane
    unsigned ob = (plane * H2_ + h2) * W4OUT + w16 * 2u; // float4 index
    const unsigned kstride = C_ * H2_ * W4OUT;           // per-subband stride in float4

    __stcs(&ov[ob],                  o0a);
    __stcs(&ov[ob + 1],              o0b);
    __stcs(&ov[ob + kstride],        o1a);
    __stcs(&ov[ob + kstride + 1],    o1b);
    __stcs(&ov[ob + 2u*kstride],     o2a);
    __stcs(&ov[ob + 2u*kstride + 1], o2b);
    __stcs(&ov[ob + 3u*kstride],     o3a);
    __stcs(&ov[ob + 3u*kstride + 1], o3b);
}

extern "C" void kernel_launch(void* const* d_in, const int* in_sizes, int n_in,
                              void* d_out, int out_size) {
    const float* x = (const float*)d_in[0];
    float* out = (float*)d_out;
    const unsigned total = N_ * C_ * H2_ * TPATCH;   // 2,097,152 threads
    dwt2_haar_kernel<<<total / 256, 256>>>(x, out);
}

// round 3
// speedup vs baseline: 1.1011x; 1.1011x over previous
#include <cuda_runtime.h>
#include <cuda_bf16.h>

// Haar 2x2 DWT: x[16,64,256,256] f32 -> out[16,256,128,128] f32
//   out[n][k*C + c][h2][w2]
//   a = x[..][2h2][2w2], b = x[..][2h2][2w2+1], cc = x[..][2h2+1][2w2], d = x[..][2h2+1][2w2+1]
//   k0 = .5(a+b+cc+d); k1 = .5(a+b-cc-d); k2 = .5(a-b+cc-d); k3 = .5(a-b-cc+d)
//
// Round 3: round-1 structure (4x LDG.128 per thread, 4x STG.128, 32 regs, occ~77%)
// + single change: evict-first (.cs) stores. Loads via __ldg as in round 1.

#define N_   16
#define C_   64
#define H_   256
#define W_   256
#define H2_  (H_/2)   // 128
#define W2_  (W_/2)   // 128
#define W4IN (W_/4)   // 64 float4 per input row
#define W4OUT (W2_/4) // 32 float4 per output row
#define TPATCH 32     // threads per row-pair: W_/8

__global__ __launch_bounds__(256, 8)
void dwt2_haar_kernel(const float* __restrict__ x, float* __restrict__ out) {
    unsigned tid = blockIdx.x * blockDim.x + threadIdx.x;
    // tid = ((n*C_ + c)*H2_ + h2)*TPATCH + w8
    unsigned w8   = tid & (TPATCH - 1);
    unsigned rest = tid >> 5;
    unsigned h2   = rest & (H2_ - 1);
    rest >>= 7;
    unsigned c    = rest & (C_ - 1);
    unsigned n    = rest >> 6;

    const float4* xv = (const float4*)x;
    unsigned row0 = (n * C_ + c) * H_ + 2u * h2;
    unsigned ib   = row0 * W4IN + w8 * 2u;

    float4 t0 = __ldg(&xv[ib]);
    float4 t1 = __ldg(&xv[ib + 1]);
    float4 b0 = __ldg(&xv[ib + W4IN]);
    float4 b1 = __ldg(&xv[ib + 1 + W4IN]);

    float4 o0, o1, o2, o3;  // subbands k=0..3, 4 output cols each

    {
        float a = t0.x, b = t0.y, cc = b0.x, d = b0.y;
        float s0 = a + b, s1 = cc + d, e0 = a - b, e1 = cc - d;
        o0.x = 0.5f*(s0+s1); o1.x = 0.5f*(s0-s1); o2.x = 0.5f*(e0+e1); o3.x = 0.5f*(e0-e1);
    }
    {
        float a = t0.z, b = t0.w, cc = b0.z, d = b0.w;
        float s0 = a + b, s1 = cc + d, e0 = a - b, e1 = cc - d;
        o0.y = 0.5f*(s0+s1); o1.y = 0.5f*(s0-s1); o2.y = 0.5f*(e0+e1); o3.y = 0.5f*(e0-e1);
    }
    {
        float a = t1.x, b = t1.y, cc = b1.x, d = b1.y;
        float s0 = a + b, s1 = cc + d, e0 = a - b, e1 = cc - d;
        o0.z = 0.5f*(s0+s1); o1.z = 0.5f*(s0-s1); o2.z = 0.5f*(e0+e1); o3.z = 0.5f*(e0-e1);
    }
    {
        float a = t1.z, b = t1.w, cc = b1.z, d = b1.w;
        float s0 = a + b, s1 = cc + d, e0 = a - b, e1 = cc - d;
        o0.w = 0.5f*(s0+s1); o1.w = 0.5f*(s0-s1); o2.w = 0.5f*(e0+e1); o3.w = 0.5f*(e0-e1);
    }

    float4* ov = (float4*)out;
    unsigned plane = n * (4u * C_) + c;                 // k=0 plane
    unsigned ob = (plane * H2_ + h2) * W4OUT + w8;
    const unsigned kstride = C_ * H2_ * W4OUT;

    __stcs(&ov[ob],              o0);
    __stcs(&ov[ob + kstride],    o1);
    __stcs(&ov[ob + 2u*kstride], o2);
    __stcs(&ov[ob + 3u*kstride], o3);
}

extern "C" void kernel_launch(void* const* d_in, const int* in_sizes, int n_in,
                              void* d_out, int out_size) {
    const float* x = (const float*)d_in[0];
    float* out = (float*)d_out;
    const unsigned total = N_ * C_ * H2_ * TPATCH;   // 4,194,304 threads
    dwt2_haar_kernel<<<total / 256, 256>>>(x, out);
}